// round 1
// baseline (speedup 1.0000x reference)
#include <cuda_runtime.h>
#include <math.h>

#define T_ 4096
#define D_ 512
#define TR_ 64
#define CC_ 64
#define L_ 3
#define F_ 8192
#define NCH_ 4096
#define NCHUNK_ 16
#define CHUNK_ 256

// ---------------- scratch (device globals: no allocation allowed) ----------------
__device__ float g_x[T_*D_];          // running x
__device__ float g_tr[T_*TR_];
__device__ float g_ct[T_*CC_];
__device__ float g_u[T_*TR_];
__device__ float g_v[T_*CC_];
__device__ float g_scaled[(size_t)T_*F_];     // 128 MiB feature buffer
__device__ float2 g_Bend[NCHUNK_*NCH_];
__device__ float2 g_Amat[NCHUNK_*NCH_];
__device__ float2 g_sinit[NCHUNK_*NCH_];
__device__ float g_h[T_*D_];          // pre-LN GEMM output
__device__ float g_z0[T_*D_];         // post LN1 activations
__device__ float g_ztmp[T_*D_];       // z output for non-final layers

// ---------------- generic NT GEMM: C[m,n] = sum_k A[m,k]*B[n,k] ----------------
template<int BM,int BN,int BK,int TM,int TN>
__global__ void __launch_bounds__((BM/TM)*(BN/TN))
gemm_nt(const float* __restrict__ A, const float* __restrict__ B,
        float* __restrict__ C, int M, int N, int K) {
  constexpr int TX = BN/TN;
  constexpr int TY = BM/TM;
  constexpr int NT = TX*TY;
  __shared__ float As[BK][BM];
  __shared__ float Bs[BK][BN];
  const int bm = blockIdx.y*BM;
  const int bn = blockIdx.x*BN;
  const int tid = threadIdx.x;
  const int tx = tid % TX;
  const int ty = tid / TX;
  float acc[TM][TN];
  #pragma unroll
  for (int i=0;i<TM;i++)
    #pragma unroll
    for (int j=0;j<TN;j++) acc[i][j]=0.f;

  constexpr int KV = BK/4;                 // float4 chunks per row
  constexpr int AIT = (BM*KV + NT - 1)/NT;
  constexpr int BIT = (BN*KV + NT - 1)/NT;

  for (int k0=0;k0<K;k0+=BK){
    #pragma unroll
    for (int it=0; it<AIT; it++){
      int idx = tid + it*NT;
      if (AIT*NT == BM*KV || idx < BM*KV){
        int row = idx / KV, kc = idx % KV;
        float4 va = *(const float4*)(A + (size_t)(bm+row)*K + k0 + kc*4);
        As[kc*4+0][row]=va.x; As[kc*4+1][row]=va.y;
        As[kc*4+2][row]=va.z; As[kc*4+3][row]=va.w;
      }
    }
    #pragma unroll
    for (int it=0; it<BIT; it++){
      int idx = tid + it*NT;
      if (BIT*NT == BN*KV || idx < BN*KV){
        int row = idx / KV, kc = idx % KV;
        float4 vb = *(const float4*)(B + (size_t)(bn+row)*K + k0 + kc*4);
        Bs[kc*4+0][row]=vb.x; Bs[kc*4+1][row]=vb.y;
        Bs[kc*4+2][row]=vb.z; Bs[kc*4+3][row]=vb.w;
      }
    }
    __syncthreads();
    #pragma unroll
    for (int k=0;k<BK;k++){
      float av[TM], bv[TN];
      #pragma unroll
      for (int i=0;i<TM;i++) av[i]=As[k][ty*TM+i];
      #pragma unroll
      for (int j=0;j<TN;j++) bv[j]=Bs[k][tx*TN+j];
      #pragma unroll
      for (int i=0;i<TM;i++)
        #pragma unroll
        for (int j=0;j<TN;j++)
          acc[i][j] = fmaf(av[i], bv[j], acc[i][j]);
    }
    __syncthreads();
  }
  #pragma unroll
  for (int i=0;i<TM;i++){
    float* crow = C + (size_t)(bm+ty*TM+i)*N + bn + tx*TN;
    #pragma unroll
    for (int j=0;j<TN;j+=4){
      float4 vv = make_float4(acc[i][j],acc[i][j+1],acc[i][j+2],acc[i][j+3]);
      *(float4*)(crow + j) = vv;
    }
  }
}

// ---------------- copy input x into running buffer ----------------
__global__ void copy_x(const float* __restrict__ src){
  int idx = blockIdx.x*blockDim.x + threadIdx.x;
  g_x[idx] = src[idx];
}

// ---------------- u, v with normalization (pre factorization) ----------------
// pre[t,i,j] = |tr_i|*|ct_j| / (1e-8 + (sum|tr|)*(sum|ct|))  -> u[t,i]*v[t,j]
__global__ void uv_kernel(){
  int t = blockIdx.x;
  int i = threadIdx.x;   // 64 threads
  float uu = fabsf(g_tr[t*TR_+i]);
  float vv = fabsf(g_ct[t*CC_+i]);
  __shared__ float su[64], sv[64];
  su[i]=uu; sv[i]=vv; __syncthreads();
  for (int s=32; s>0; s>>=1){
    if (i<s){ su[i]+=su[i+s]; sv[i]+=sv[i+s]; }
    __syncthreads();
  }
  float scale = __fdividef(1.0f, 1e-8f + su[0]*sv[0]);
  g_u[t*TR_+i] = uu;
  g_v[t*CC_+i] = vv*scale;
}

// ---------------- decay constant per channel (double-precision setup) ----------------
__device__ __forceinline__ void make_decay(float ai, float bj, float& dre, float& dim){
  double rho = exp(-(double)fabsf(ai));
  double sb, cb; sincos((double)bj, &sb, &cb);
  dre = (float)(rho*cb); dim = (float)(rho*sb);
}

// ---------------- scan pass A: per-chunk summary (B_end, A) ----------------
__global__ void scan_passA(const unsigned* __restrict__ start,
                           const float* __restrict__ a, const float* __restrict__ b,
                           int layer){
  const int i = blockIdx.y;
  const int c = blockIdx.x;
  const int j = threadIdx.x;
  const float ai = a[layer*TR_ + i];
  const float bj = b[layer*CC_ + j];
  float dre, dim;
  make_decay(ai, bj, dre, dim);
  float sre=0.f, sim=0.f;
  int reset = 0;
  const int t0 = c*CHUNK_;
  for (int t=t0; t<t0+CHUNK_; t++){
    if (start[t]){ sre=0.f; sim=0.f; reset=1; }
    float p = g_u[t*TR_+i]*g_v[t*CC_+j];
    float nre = fmaf(sre,dre, fmaf(-sim,dim,p));
    float nim = fmaf(sre,dim, sim*dre);
    sre=nre; sim=nim;
  }
  const int ch = i*CC_+j;
  g_Bend[c*NCH_+ch]=make_float2(sre,sim);
  float2 A;
  if (reset){ A=make_float2(0.f,0.f); }
  else {
    double rhoL = exp(-(double)fabsf(ai)*(double)CHUNK_);
    double sL,cL; sincos((double)bj*(double)CHUNK_, &sL,&cL);
    A = make_float2((float)(rhoL*cL), (float)(rhoL*sL));
  }
  g_Amat[c*NCH_+ch]=A;
}

// ---------------- scan pass B: sequential chunk combine (tiny) ----------------
__global__ void scan_passB(const float* __restrict__ state, int layer){
  int ch = blockIdx.x*blockDim.x + threadIdx.x;  // 4096 channels
  float sre = state[layer*NCH_ + ch];            // (L,1,TR,CC), real init
  float sim = 0.f;
  #pragma unroll
  for (int c=0;c<NCHUNK_;c++){
    g_sinit[c*NCH_+ch] = make_float2(sre,sim);
    float2 A = g_Amat[c*NCH_+ch];
    float2 B = g_Bend[c*NCH_+ch];
    float nre = A.x*sre - A.y*sim + B.x;
    float nim = A.x*sim + A.y*sre + B.y;
    sre=nre; sim=nim;
  }
}

// ---------------- scan pass C: full scan + feature emission ----------------
// scaled[t, ch]       = log1p(r)*im/r   (mag*sin(angle))
// scaled[t, 4096+ch]  = log1p(r)*re/r   (mag*cos(angle))
__global__ void scan_passC(const unsigned* __restrict__ start,
                           const float* __restrict__ a, const float* __restrict__ b,
                           int layer){
  const int i = blockIdx.y, c = blockIdx.x, j = threadIdx.x;
  float dre, dim;
  make_decay(a[layer*TR_+i], b[layer*CC_+j], dre, dim);
  const int ch = i*CC_+j;
  float2 s0 = g_sinit[c*NCH_+ch];
  float sre=s0.x, sim=s0.y;
  const int t0=c*CHUNK_;
  for (int t=t0;t<t0+CHUNK_;t++){
    if (start[t]){ sre=0.f; sim=0.f; }
    float p = g_u[t*TR_+i]*g_v[t*CC_+j];
    float nre = fmaf(sre,dre, fmaf(-sim,dim,p));
    float nim = fmaf(sre,dim, sim*dre);
    sre=nre; sim=nim;
    float r2 = fmaf(sre,sre, sim*sim);
    float f;
    if (r2 > 1e-24f){
      float r = sqrtf(r2);
      f = __fdividef(log1pf(r), r);
    } else {
      f = 1.f;   // log1p(r)/r -> 1 as r -> 0
    }
    g_scaled[(size_t)t*F_ + ch]        = f*sim;
    g_scaled[(size_t)t*F_ + NCH_ + ch] = f*sre;
  }
}

// ---------------- LayerNorm + leaky ReLU (+ optional residual accumulate) ----------------
__device__ __forceinline__ void reduce2(float &s, float &ss){
  __shared__ float sh[8], sh2[8];
  int lane = threadIdx.x & 31, w = threadIdx.x >> 5;
  #pragma unroll
  for (int o=16;o>0;o>>=1){
    s  += __shfl_down_sync(0xffffffffu, s,  o);
    ss += __shfl_down_sync(0xffffffffu, ss, o);
  }
  if (lane==0){ sh[w]=s; sh2[w]=ss; }
  __syncthreads();
  if (w==0){
    s  = (lane<8)? sh[lane]  : 0.f;
    ss = (lane<8)? sh2[lane] : 0.f;
    #pragma unroll
    for (int o=4;o>0;o>>=1){
      s  += __shfl_down_sync(0xffffffffu, s,  o);
      ss += __shfl_down_sync(0xffffffffu, ss, o);
    }
    if (lane==0){ sh[0]=s; sh2[0]=ss; }
  }
  __syncthreads();
  s = sh[0]; ss = sh2[0];
}

__global__ void ln_leaky(const float* __restrict__ zin, const float* __restrict__ bias,
                         const float* __restrict__ gamma, const float* __restrict__ beta,
                         float* __restrict__ zout, float* __restrict__ xacc){
  const int t = blockIdx.x;
  const int tid = threadIdx.x;   // 256 threads, 2 cols each
  float v0 = zin[t*D_ + tid]       + bias[tid];
  float v1 = zin[t*D_ + 256 + tid] + bias[256+tid];
  float s = v0+v1;
  float ss = v0*v0 + v1*v1;
  reduce2(s, ss);
  float m = s * (1.f/512.f);
  float var = ss * (1.f/512.f) - m*m;
  float rinv = rsqrtf(var + 1e-5f);
  float y0 = (v0 - m)*rinv*gamma[tid]     + beta[tid];
  float y1 = (v1 - m)*rinv*gamma[256+tid] + beta[256+tid];
  y0 = (y0 > 0.f) ? y0 : 0.01f*y0;
  y1 = (y1 > 0.f) ? y1 : 0.01f*y1;
  zout[t*D_ + tid]       = y0;
  zout[t*D_ + 256 + tid] = y1;
  if (xacc){
    xacc[t*D_ + tid]       += y0;
    xacc[t*D_ + 256 + tid] += y1;
  }
}

// ---------------- launcher ----------------
extern "C" void kernel_launch(void* const* d_in, const int* in_sizes, int n_in,
                              void* d_out, int out_size) {
  const float*    x     = (const float*)d_in[0];
  const float*    state = (const float*)d_in[1];
  const unsigned* start = (const unsigned*)d_in[2];  // bool stored as 4-byte (int32/f32): nonzero = true
  const float*    Wtr   = (const float*)d_in[3];
  const float*    Wc    = (const float*)d_in[4];
  const float*    a     = (const float*)d_in[5];
  const float*    b     = (const float*)d_in[6];
  const float*    W0    = (const float*)d_in[7];
  const float*    b0    = (const float*)d_in[8];
  const float*    g0    = (const float*)d_in[9];
  const float*    beta0 = (const float*)d_in[10];
  const float*    W1    = (const float*)d_in[11];
  const float*    b1    = (const float*)d_in[12];
  const float*    g1    = (const float*)d_in[13];
  const float*    beta1 = (const float*)d_in[14];
  float* out = (float*)d_out;

  float *px, *ptr, *pct, *psc, *ph, *pz0, *pzt;
  cudaGetSymbolAddress((void**)&px,  g_x);
  cudaGetSymbolAddress((void**)&ptr, g_tr);
  cudaGetSymbolAddress((void**)&pct, g_ct);
  cudaGetSymbolAddress((void**)&psc, g_scaled);
  cudaGetSymbolAddress((void**)&ph,  g_h);
  cudaGetSymbolAddress((void**)&pz0, g_z0);
  cudaGetSymbolAddress((void**)&pzt, g_ztmp);

  copy_x<<<(T_*D_)/256, 256>>>(x);

  for (int l=0; l<L_; l++){
    // tr = x @ Wtr[l].T ; ct = x @ Wc[l].T   (M=4096, N=64, K=512)
    gemm_nt<32,64,16,4,4><<<dim3(1, T_/32), 128>>>(px, Wtr + (size_t)l*TR_*D_, ptr, T_, TR_, D_);
    gemm_nt<32,64,16,4,4><<<dim3(1, T_/32), 128>>>(px, Wc  + (size_t)l*CC_*D_, pct, T_, CC_, D_);
    uv_kernel<<<T_, 64>>>();

    // chunked complex scan with resets
    scan_passA<<<dim3(NCHUNK_, TR_), CC_>>>(start, a, b, l);
    scan_passB<<<NCH_/256, 256>>>(state, l);
    scan_passC<<<dim3(NCHUNK_, TR_), CC_>>>(start, a, b, l);

    // z0 = leaky(LN(scaled @ W0[l].T + b0))   (M=4096, N=512, K=8192)
    gemm_nt<128,128,16,8,8><<<dim3(D_/128, T_/128), 256>>>(psc, W0 + (size_t)l*D_*F_, ph, T_, D_, F_);
    ln_leaky<<<T_, 256>>>(ph, b0 + l*D_, g0 + l*D_, beta0 + l*D_, pz0, nullptr);

    // z = leaky(LN(z0 @ W1[l].T + b1)) ; x += z   (M=4096, N=512, K=512)
    gemm_nt<128,128,16,8,8><<<dim3(D_/128, T_/128), 256>>>(pz0, W1 + (size_t)l*D_*D_, ph, T_, D_, D_);
    float* zo = (l == L_-1) ? out : pzt;
    ln_leaky<<<T_, 256>>>(ph, b1 + l*D_, g1 + l*D_, beta1 + l*D_, zo, px);
  }
}

// round 3
// speedup vs baseline: 2.1853x; 2.1853x over previous
#include <cuda_runtime.h>
#include <cuda_bf16.h>
#include <math.h>
#include <stdint.h>

#define T_ 4096
#define D_ 512
#define TR_ 64
#define CC_ 64
#define L_ 3
#define F_ 8192
#define NCH_ 4096
#define NCHUNK_ 16
#define CHUNK_ 256

// ---------------- scratch ----------------
__device__ float g_x[T_*D_];
__device__ float g_tr[T_*TR_];
__device__ float g_ct[T_*CC_];
__device__ float g_u[T_*TR_];
__device__ float g_v[T_*CC_];
__device__ float2 g_Bend[NCHUNK_*NCH_];
__device__ float2 g_Amat[NCHUNK_*NCH_];
__device__ float2 g_sinit[NCHUNK_*NCH_];
__device__ float g_h[T_*D_];
__device__ float g_ztmp[T_*D_];
__device__ __nv_bfloat16 g_sclhi[(size_t)T_*F_];
__device__ __nv_bfloat16 g_scllo[(size_t)T_*F_];
__device__ __nv_bfloat16 g_w0hi[L_*D_*F_];
__device__ __nv_bfloat16 g_w0lo[L_*D_*F_];
__device__ __nv_bfloat16 g_w1hi[L_*D_*D_];
__device__ __nv_bfloat16 g_w1lo[L_*D_*D_];
__device__ __nv_bfloat16 g_z0hi[T_*D_];
__device__ __nv_bfloat16 g_z0lo[T_*D_];

// ---------------- low-level helpers (baseline PTX, compiles at compute_103) ----------------
__device__ __forceinline__ uint32_t sptr(const void* p){
  return (uint32_t)__cvta_generic_to_shared(p);
}
__device__ __forceinline__ void cp16(uint32_t s, const void* g){
  asm volatile("cp.async.cg.shared.global [%0], [%1], 16;" :: "r"(s), "l"(g));
}
#define CP_COMMIT() asm volatile("cp.async.commit_group;" ::: "memory")
#define CP_WAIT(n)  asm volatile("cp.async.wait_group %0;" :: "n"(n) : "memory")

__device__ __forceinline__ void ldsm4(uint32_t* r, uint32_t a){
  asm volatile("ldmatrix.sync.aligned.m8n8.x4.shared.b16 {%0,%1,%2,%3}, [%4];"
    : "=r"(r[0]),"=r"(r[1]),"=r"(r[2]),"=r"(r[3]) : "r"(a));
}
__device__ __forceinline__ void mma16816(float* d, const uint32_t* a, const uint32_t* b){
  asm volatile("mma.sync.aligned.m16n8k16.row.col.f32.bf16.bf16.f32 "
    "{%0,%1,%2,%3}, {%4,%5,%6,%7}, {%8,%9}, {%0,%1,%2,%3};"
    : "+f"(d[0]),"+f"(d[1]),"+f"(d[2]),"+f"(d[3])
    : "r"(a[0]),"r"(a[1]),"r"(a[2]),"r"(a[3]), "r"(b[0]),"r"(b[1]));
}

// ---------------- split fp32 -> bf16 hi/lo ----------------
__global__ void split_f32(const float* __restrict__ src, __nv_bfloat16* __restrict__ hi,
                          __nv_bfloat16* __restrict__ lo, int n){
  int i = blockIdx.x*blockDim.x + threadIdx.x;
  if (i < n){
    float v = src[i];
    __nv_bfloat16 h = __float2bfloat16(v);
    hi[i] = h;
    lo[i] = __float2bfloat16(v - __bfloat162float(h));
  }
}

// ================= mma.sync split-bf16 GEMM =================
// C[m,n] = sum_k A[m,k]*B[n,k], fp32 acc, 3-term split.
// BM=BN=128, BK=32, 256 threads (8 warps, 4x2), warp tile 32x64.
#define PADB 40                    // bf16 per SMEM row (32 data + 8 pad)
#define TILE_E (128*PADB)          // bf16 per tile
#define STAGE_E (4*TILE_E)         // Ahi,Alo,Bhi,Blo
#define GEMM_SMEM (2*STAGE_E*2)    // bytes (2 stages) = 81920

__device__ __forceinline__ void stage_load(
    __nv_bfloat16* s, const __nv_bfloat16* Ahi, const __nv_bfloat16* Alo,
    const __nv_bfloat16* Bhi, const __nv_bfloat16* Blo,
    int bm, int bn, int K, int k0, int tid)
{
  const __nv_bfloat16* src[4] = {Ahi, Alo, Bhi, Blo};
  #pragma unroll
  for (int t=0;t<4;t++){
    int rb = (t<2)? bm : bn;
    #pragma unroll
    for (int q=0;q<2;q++){
      int chunk = tid + q*256;          // 512 16B-chunks per tile
      int row = chunk>>2, cc = chunk&3;
      uint32_t so = sptr(s + t*TILE_E + row*PADB + cc*8);
      cp16(so, src[t] + (size_t)(rb+row)*K + k0 + cc*8);
    }
  }
}

__global__ void __launch_bounds__(256)
gemm_mma3(const __nv_bfloat16* __restrict__ Ahi, const __nv_bfloat16* __restrict__ Alo,
          const __nv_bfloat16* __restrict__ Bhi, const __nv_bfloat16* __restrict__ Blo,
          float* __restrict__ C, int K, int Nc)
{
  extern __shared__ __nv_bfloat16 sm[];
  const int tid = threadIdx.x;
  const int wid = tid>>5, lane = tid&31;
  const int bm = blockIdx.y*128, bn = blockIdx.x*128;
  const int wm = (wid>>1)*32;
  const int wn = (wid&1)*64;
  const int KT = K>>5;

  float acc[2][8][4];
  #pragma unroll
  for (int i=0;i<2;i++)
    #pragma unroll
    for (int j=0;j<8;j++)
      #pragma unroll
      for (int q=0;q<4;q++) acc[i][j][q]=0.f;

  stage_load(sm, Ahi, Alo, Bhi, Blo, bm, bn, K, 0, tid);
  CP_COMMIT();

  // precomputed ldmatrix lane offsets
  const int arow = lane & 15;
  const int acol8 = (lane>>4)*8;              // +8 bf16 for k8..15 half
  const int brow = (lane&7) + ((lane>>4)<<3); // n within 16-group
  const int bsel = ((lane>>3)&1)*8;           // k half

  for (int c=0; c<KT; c++){
    if (c+1 < KT){
      stage_load(sm + ((c+1)&1)*STAGE_E, Ahi, Alo, Bhi, Blo, bm, bn, K, (c+1)*32, tid);
      CP_COMMIT();
      CP_WAIT(1);
    } else {
      CP_WAIT(0);
    }
    __syncthreads();

    __nv_bfloat16* s = sm + (c&1)*STAGE_E;
    const uint32_t sA_hi = sptr(s);
    const uint32_t sA_lo = sA_hi + TILE_E*2;
    const uint32_t sB_hi = sA_hi + 2*TILE_E*2;
    const uint32_t sB_lo = sA_hi + 3*TILE_E*2;

    #pragma unroll
    for (int ks=0; ks<2; ks++){
      uint32_t ah[2][4], al[2][4], bh[4][4], bl[4][4];
      #pragma unroll
      for (int mi=0; mi<2; mi++){
        uint32_t off = (uint32_t)((wm + mi*16 + arow)*PADB + ks*16 + acol8)*2;
        ldsm4(ah[mi], sA_hi + off);
        ldsm4(al[mi], sA_lo + off);
      }
      #pragma unroll
      for (int p=0; p<4; p++){
        uint32_t off = (uint32_t)((wn + p*16 + brow)*PADB + ks*16 + bsel)*2;
        ldsm4(bh[p], sB_hi + off);
        ldsm4(bl[p], sB_lo + off);
      }
      #pragma unroll
      for (int mi=0; mi<2; mi++)
        #pragma unroll
        for (int p=0; p<4; p++)
          #pragma unroll
          for (int h=0; h<2; h++){
            const int ni = p*2 + h;
            mma16816(acc[mi][ni], ah[mi], &bh[p][h*2]);
            mma16816(acc[mi][ni], ah[mi], &bl[p][h*2]);
            mma16816(acc[mi][ni], al[mi], &bh[p][h*2]);
          }
    }
    __syncthreads();
  }

  // epilogue
  #pragma unroll
  for (int mi=0; mi<2; mi++){
    const int r0 = bm + wm + mi*16 + (lane>>2);
    const int c0 = bn + wn + (lane&3)*2;
    #pragma unroll
    for (int ni=0; ni<8; ni++){
      float2 v01 = make_float2(acc[mi][ni][0], acc[mi][ni][1]);
      float2 v23 = make_float2(acc[mi][ni][2], acc[mi][ni][3]);
      *(float2*)(C + (size_t)r0*Nc + c0 + ni*8)     = v01;
      *(float2*)(C + (size_t)(r0+8)*Nc + c0 + ni*8) = v23;
    }
  }
}

// ================= fp32 SIMT GEMM (small projections) =================
template<int BM,int BN,int BK,int TM,int TN>
__global__ void __launch_bounds__((BM/TM)*(BN/TN))
gemm_nt(const float* __restrict__ A, const float* __restrict__ B,
        float* __restrict__ C, int M, int N, int K) {
  constexpr int TX = BN/TN;
  constexpr int TY = BM/TM;
  constexpr int NT = TX*TY;
  __shared__ float As[BK][BM];
  __shared__ float Bs[BK][BN];
  const int bm = blockIdx.y*BM;
  const int bn = blockIdx.x*BN;
  const int tid = threadIdx.x;
  const int tx = tid % TX;
  const int ty = tid / TX;
  float acc[TM][TN];
  #pragma unroll
  for (int i=0;i<TM;i++)
    #pragma unroll
    for (int j=0;j<TN;j++) acc[i][j]=0.f;
  constexpr int KV = BK/4;
  constexpr int AIT = (BM*KV + NT - 1)/NT;
  constexpr int BIT = (BN*KV + NT - 1)/NT;
  for (int k0=0;k0<K;k0+=BK){
    #pragma unroll
    for (int it=0; it<AIT; it++){
      int idx = tid + it*NT;
      if (AIT*NT == BM*KV || idx < BM*KV){
        int row = idx / KV, kcc = idx % KV;
        float4 va = *(const float4*)(A + (size_t)(bm+row)*K + k0 + kcc*4);
        As[kcc*4+0][row]=va.x; As[kcc*4+1][row]=va.y;
        As[kcc*4+2][row]=va.z; As[kcc*4+3][row]=va.w;
      }
    }
    #pragma unroll
    for (int it=0; it<BIT; it++){
      int idx = tid + it*NT;
      if (BIT*NT == BN*KV || idx < BN*KV){
        int row = idx / KV, kcc = idx % KV;
        float4 vb = *(const float4*)(B + (size_t)(bn+row)*K + k0 + kcc*4);
        Bs[kcc*4+0][row]=vb.x; Bs[kcc*4+1][row]=vb.y;
        Bs[kcc*4+2][row]=vb.z; Bs[kcc*4+3][row]=vb.w;
      }
    }
    __syncthreads();
    #pragma unroll
    for (int k=0;k<BK;k++){
      float av[TM], bv[TN];
      #pragma unroll
      for (int i=0;i<TM;i++) av[i]=As[k][ty*TM+i];
      #pragma unroll
      for (int j=0;j<TN;j++) bv[j]=Bs[k][tx*TN+j];
      #pragma unroll
      for (int i=0;i<TM;i++)
        #pragma unroll
        for (int j=0;j<TN;j++)
          acc[i][j] = fmaf(av[i], bv[j], acc[i][j]);
    }
    __syncthreads();
  }
  #pragma unroll
  for (int i=0;i<TM;i++){
    float* crow = C + (size_t)(bm+ty*TM+i)*N + bn + tx*TN;
    #pragma unroll
    for (int j=0;j<TN;j+=4){
      float4 vv = make_float4(acc[i][j],acc[i][j+1],acc[i][j+2],acc[i][j+3]);
      *(float4*)(crow + j) = vv;
    }
  }
}

__global__ void copy_x(const float* __restrict__ src){
  int idx = blockIdx.x*blockDim.x + threadIdx.x;
  g_x[idx] = src[idx];
}

// pre[t,i,j] = |tr_i|*|ct_j| / (1e-8 + sum|tr|*sum|ct|) -> u[t,i]*v[t,j]
__global__ void uv_kernel(){
  int t = blockIdx.x;
  int i = threadIdx.x;
  float uu = fabsf(g_tr[t*TR_+i]);
  float vv = fabsf(g_ct[t*CC_+i]);
  __shared__ float su[64], sv[64];
  su[i]=uu; sv[i]=vv; __syncthreads();
  for (int s=32; s>0; s>>=1){
    if (i<s){ su[i]+=su[i+s]; sv[i]+=sv[i+s]; }
    __syncthreads();
  }
  float scale = __fdividef(1.0f, 1e-8f + su[0]*sv[0]);
  g_u[t*TR_+i] = uu;
  g_v[t*CC_+i] = vv*scale;
}

__device__ __forceinline__ void make_decay(float ai, float bj, float& dre, float& dim){
  double rho = exp(-(double)fabsf(ai));
  double sb, cb; sincos((double)bj, &sb, &cb);
  dre = (float)(rho*cb); dim = (float)(rho*sb);
}

__global__ void scan_passA(const unsigned* __restrict__ start,
                           const float* __restrict__ a, const float* __restrict__ b,
                           int layer){
  const int i = blockIdx.y;
  const int c = blockIdx.x;
  const int j = threadIdx.x;
  const float ai = a[layer*TR_ + i];
  const float bj = b[layer*CC_ + j];
  float dre, dim;
  make_decay(ai, bj, dre, dim);
  float sre=0.f, sim=0.f;
  int reset = 0;
  const int t0 = c*CHUNK_;
  for (int t=t0; t<t0+CHUNK_; t++){
    if (start[t]){ sre=0.f; sim=0.f; reset=1; }
    float p = g_u[t*TR_+i]*g_v[t*CC_+j];
    float nre = fmaf(sre,dre, fmaf(-sim,dim,p));
    float nim = fmaf(sre,dim, sim*dre);
    sre=nre; sim=nim;
  }
  const int ch = i*CC_+j;
  g_Bend[c*NCH_+ch]=make_float2(sre,sim);
  float2 A;
  if (reset){ A=make_float2(0.f,0.f); }
  else {
    double rhoL = exp(-(double)fabsf(ai)*(double)CHUNK_);
    double sL,cL; sincos((double)bj*(double)CHUNK_, &sL,&cL);
    A = make_float2((float)(rhoL*cL), (float)(rhoL*sL));
  }
  g_Amat[c*NCH_+ch]=A;
}

__global__ void scan_passB(const float* __restrict__ state, int layer){
  int ch = blockIdx.x*blockDim.x + threadIdx.x;
  float sre = state[layer*NCH_ + ch];
  float sim = 0.f;
  #pragma unroll
  for (int c=0;c<NCHUNK_;c++){
    g_sinit[c*NCH_+ch] = make_float2(sre,sim);
    float2 A = g_Amat[c*NCH_+ch];
    float2 B = g_Bend[c*NCH_+ch];
    float nre = A.x*sre - A.y*sim + B.x;
    float nim = A.x*sim + A.y*sre + B.y;
    sre=nre; sim=nim;
  }
}

// full scan + feature emission directly in bf16 hi/lo
__global__ void scan_passC(const unsigned* __restrict__ start,
                           const float* __restrict__ a, const float* __restrict__ b,
                           int layer){
  const int i = blockIdx.y, c = blockIdx.x, j = threadIdx.x;
  float dre, dim;
  make_decay(a[layer*TR_+i], b[layer*CC_+j], dre, dim);
  const int ch = i*CC_+j;
  float2 s0 = g_sinit[c*NCH_+ch];
  float sre=s0.x, sim=s0.y;
  const int t0=c*CHUNK_;
  for (int t=t0;t<t0+CHUNK_;t++){
    if (start[t]){ sre=0.f; sim=0.f; }
    float p = g_u[t*TR_+i]*g_v[t*CC_+j];
    float nre = fmaf(sre,dre, fmaf(-sim,dim,p));
    float nim = fmaf(sre,dim, sim*dre);
    sre=nre; sim=nim;
    float r2 = fmaf(sre,sre, sim*sim);
    float f;
    if (r2 > 1e-24f){
      float rr = sqrtf(r2);
      f = __fdividef(log1pf(rr), rr);
    } else {
      f = 1.f;
    }
    float fs = f*sim, fc = f*sre;
    __nv_bfloat16 h0 = __float2bfloat16(fs);
    __nv_bfloat16 h1 = __float2bfloat16(fc);
    size_t o0 = (size_t)t*F_ + ch;
    size_t o1 = o0 + NCH_;
    g_sclhi[o0] = h0; g_scllo[o0] = __float2bfloat16(fs - __bfloat162float(h0));
    g_sclhi[o1] = h1; g_scllo[o1] = __float2bfloat16(fc - __bfloat162float(h1));
  }
}

// ================= LayerNorm + leaky ReLU =================
__device__ __forceinline__ void reduce2(float &s, float &ss){
  __shared__ float sh[8], sh2[8];
  int lane = threadIdx.x & 31, w = threadIdx.x >> 5;
  #pragma unroll
  for (int o=16;o>0;o>>=1){
    s  += __shfl_down_sync(0xffffffffu, s,  o);
    ss += __shfl_down_sync(0xffffffffu, ss, o);
  }
  if (lane==0){ sh[w]=s; sh2[w]=ss; }
  __syncthreads();
  if (w==0){
    s  = (lane<8)? sh[lane]  : 0.f;
    ss = (lane<8)? sh2[lane] : 0.f;
    #pragma unroll
    for (int o=4;o>0;o>>=1){
      s  += __shfl_down_sync(0xffffffffu, s,  o);
      ss += __shfl_down_sync(0xffffffffu, ss, o);
    }
    if (lane==0){ sh[0]=s; sh2[0]=ss; }
  }
  __syncthreads();
  s = sh[0]; ss = sh2[0];
}

__global__ void ln_leaky(const float* __restrict__ zin, const float* __restrict__ bias,
                         const float* __restrict__ gamma, const float* __restrict__ beta,
                         float* __restrict__ zout, float* __restrict__ xacc,
                         __nv_bfloat16* __restrict__ zhi, __nv_bfloat16* __restrict__ zlo){
  const int t = blockIdx.x;
  const int tid = threadIdx.x;
  float v0 = zin[t*D_ + tid]       + bias[tid];
  float v1 = zin[t*D_ + 256 + tid] + bias[256+tid];
  float s = v0+v1;
  float ss = v0*v0 + v1*v1;
  reduce2(s, ss);
  float m = s * (1.f/512.f);
  float var = ss * (1.f/512.f) - m*m;
  float rinv = rsqrtf(var + 1e-5f);
  float y0 = (v0 - m)*rinv*gamma[tid]     + beta[tid];
  float y1 = (v1 - m)*rinv*gamma[256+tid] + beta[256+tid];
  y0 = (y0 > 0.f) ? y0 : 0.01f*y0;
  y1 = (y1 > 0.f) ? y1 : 0.01f*y1;
  if (zout){
    zout[t*D_ + tid]       = y0;
    zout[t*D_ + 256 + tid] = y1;
  }
  if (xacc){
    xacc[t*D_ + tid]       += y0;
    xacc[t*D_ + 256 + tid] += y1;
  }
  if (zhi){
    __nv_bfloat16 h0 = __float2bfloat16(y0);
    __nv_bfloat16 h1 = __float2bfloat16(y1);
    zhi[t*D_ + tid]       = h0;
    zhi[t*D_ + 256 + tid] = h1;
    zlo[t*D_ + tid]       = __float2bfloat16(y0 - __bfloat162float(h0));
    zlo[t*D_ + 256 + tid] = __float2bfloat16(y1 - __bfloat162float(h1));
  }
}

// ================= launcher =================
extern "C" void kernel_launch(void* const* d_in, const int* in_sizes, int n_in,
                              void* d_out, int out_size) {
  const float*    x     = (const float*)d_in[0];
  const float*    state = (const float*)d_in[1];
  const unsigned* start = (const unsigned*)d_in[2];
  const float*    Wtr   = (const float*)d_in[3];
  const float*    Wc    = (const float*)d_in[4];
  const float*    a     = (const float*)d_in[5];
  const float*    b     = (const float*)d_in[6];
  const float*    W0    = (const float*)d_in[7];
  const float*    b0    = (const float*)d_in[8];
  const float*    g0    = (const float*)d_in[9];
  const float*    beta0 = (const float*)d_in[10];
  const float*    W1    = (const float*)d_in[11];
  const float*    b1    = (const float*)d_in[12];
  const float*    g1    = (const float*)d_in[13];
  const float*    beta1 = (const float*)d_in[14];
  float* out = (float*)d_out;

  float *px, *ptr, *pct, *ph, *pzt;
  __nv_bfloat16 *pshi, *pslo, *pw0h, *pw0l, *pw1h, *pw1l, *pz0h, *pz0l;
  cudaGetSymbolAddress((void**)&px,  g_x);
  cudaGetSymbolAddress((void**)&ptr, g_tr);
  cudaGetSymbolAddress((void**)&pct, g_ct);
  cudaGetSymbolAddress((void**)&ph,  g_h);
  cudaGetSymbolAddress((void**)&pzt, g_ztmp);
  cudaGetSymbolAddress((void**)&pshi, g_sclhi);
  cudaGetSymbolAddress((void**)&pslo, g_scllo);
  cudaGetSymbolAddress((void**)&pw0h, g_w0hi);
  cudaGetSymbolAddress((void**)&pw0l, g_w0lo);
  cudaGetSymbolAddress((void**)&pw1h, g_w1hi);
  cudaGetSymbolAddress((void**)&pw1l, g_w1lo);
  cudaGetSymbolAddress((void**)&pz0h, g_z0hi);
  cudaGetSymbolAddress((void**)&pz0l, g_z0lo);

  cudaFuncSetAttribute(gemm_mma3, cudaFuncAttributeMaxDynamicSharedMemorySize, GEMM_SMEM);

  copy_x<<<(T_*D_)/256, 256>>>(x);
  split_f32<<<(L_*D_*F_ + 255)/256, 256>>>(W0, pw0h, pw0l, L_*D_*F_);
  split_f32<<<(L_*D_*D_ + 255)/256, 256>>>(W1, pw1h, pw1l, L_*D_*D_);

  for (int l=0; l<L_; l++){
    gemm_nt<32,64,16,4,4><<<dim3(1, T_/32), 128>>>(px, Wtr + (size_t)l*TR_*D_, ptr, T_, TR_, D_);
    gemm_nt<32,64,16,4,4><<<dim3(1, T_/32), 128>>>(px, Wc  + (size_t)l*CC_*D_, pct, T_, CC_, D_);
    uv_kernel<<<T_, 64>>>();

    scan_passA<<<dim3(NCHUNK_, TR_), CC_>>>(start, a, b, l);
    scan_passB<<<NCH_/256, 256>>>(state, l);
    scan_passC<<<dim3(NCHUNK_, TR_), CC_>>>(start, a, b, l);

    // h = scaled @ W0^T   (M=4096, N=512, K=8192) on mma.sync bf16x3
    gemm_mma3<<<dim3(D_/128, T_/128), 256, GEMM_SMEM>>>(
        pshi, pslo, pw0h + (size_t)l*D_*F_, pw0l + (size_t)l*D_*F_, ph, F_, D_);
    ln_leaky<<<T_, 256>>>(ph, b0 + l*D_, g0 + l*D_, beta0 + l*D_,
                          nullptr, nullptr, pz0h, pz0l);

    // h = z0 @ W1^T   (M=4096, N=512, K=512) on mma.sync bf16x3
    gemm_mma3<<<dim3(D_/128, T_/128), 256, GEMM_SMEM>>>(
        pz0h, pz0l, pw1h + (size_t)l*D_*D_, pw1l + (size_t)l*D_*D_, ph, D_, D_);
    float* zo = (l == L_-1) ? out : pzt;
    ln_leaky<<<T_, 256>>>(ph, b1 + l*D_, g1 + l*D_, beta1 + l*D_,
                          zo, px, nullptr, nullptr);
  }
}

// round 4
// speedup vs baseline: 2.5286x; 1.1571x over previous
#include <cuda_runtime.h>
#include <cuda_bf16.h>
#include <math.h>
#include <stdint.h>

#define T_ 4096
#define D_ 512
#define TR_ 64
#define CC_ 64
#define L_ 3
#define F_ 8192
#define NCH_ 4096
#define NCHUNK_ 16
#define CHUNK_ 256

// ---------------- scratch ----------------
__device__ float g_x[T_*D_];
__device__ float g_trct[T_*128];
__device__ float g_u[T_*TR_];
__device__ float g_v[T_*CC_];
__device__ float2 g_Bend[NCHUNK_*NCH_];
__device__ float2 g_Amat[NCHUNK_*NCH_];
__device__ float2 g_sinit[NCHUNK_*NCH_];
__device__ float g_h[T_*D_];
__device__ float g_ztmp[T_*D_];
__device__ __nv_bfloat16 g_sclhi[(size_t)T_*F_];
__device__ __nv_bfloat16 g_scllo[(size_t)T_*F_];
__device__ __nv_bfloat16 g_w0hi[L_*D_*F_];
__device__ __nv_bfloat16 g_w0lo[L_*D_*F_];
__device__ __nv_bfloat16 g_w1hi[L_*D_*D_];
__device__ __nv_bfloat16 g_w1lo[L_*D_*D_];
__device__ __nv_bfloat16 g_wphi[L_*128*D_];
__device__ __nv_bfloat16 g_wplo[L_*128*D_];
__device__ __nv_bfloat16 g_z0hi[T_*D_];
__device__ __nv_bfloat16 g_z0lo[T_*D_];
__device__ __nv_bfloat16 g_xhi[T_*D_];
__device__ __nv_bfloat16 g_xlo[T_*D_];

// ---------------- low-level helpers (baseline PTX @ compute_103) ----------------
__device__ __forceinline__ uint32_t sptr(const void* p){
  return (uint32_t)__cvta_generic_to_shared(p);
}
__device__ __forceinline__ void cp16(uint32_t s, const void* g){
  asm volatile("cp.async.cg.shared.global [%0], [%1], 16;" :: "r"(s), "l"(g));
}
#define CP_COMMIT() asm volatile("cp.async.commit_group;" ::: "memory")
#define CP_WAIT(n)  asm volatile("cp.async.wait_group %0;" :: "n"(n) : "memory")

__device__ __forceinline__ void ldsm4(uint32_t* r, uint32_t a){
  asm volatile("ldmatrix.sync.aligned.m8n8.x4.shared.b16 {%0,%1,%2,%3}, [%4];"
    : "=r"(r[0]),"=r"(r[1]),"=r"(r[2]),"=r"(r[3]) : "r"(a));
}
__device__ __forceinline__ void mma16816(float* d, const uint32_t* a, const uint32_t* b){
  asm volatile("mma.sync.aligned.m16n8k16.row.col.f32.bf16.bf16.f32 "
    "{%0,%1,%2,%3}, {%4,%5,%6,%7}, {%8,%9}, {%0,%1,%2,%3};"
    : "+f"(d[0]),"+f"(d[1]),"+f"(d[2]),"+f"(d[3])
    : "r"(a[0]),"r"(a[1]),"r"(a[2]),"r"(a[3]), "r"(b[0]),"r"(b[1]));
}

// ---------------- split fp32 -> bf16 hi/lo ----------------
__global__ void split_f32(const float* __restrict__ src, __nv_bfloat16* __restrict__ hi,
                          __nv_bfloat16* __restrict__ lo, int n){
  int i = blockIdx.x*blockDim.x + threadIdx.x;
  if (i < n){
    float v = src[i];
    __nv_bfloat16 h = __float2bfloat16(v);
    hi[i] = h;
    lo[i] = __float2bfloat16(v - __bfloat162float(h));
  }
}

// copy input x -> g_x AND split to bf16 hi/lo
__global__ void copy_split_x(const float* __restrict__ src){
  int i = blockIdx.x*blockDim.x + threadIdx.x;
  float v = src[i];
  g_x[i] = v;
  __nv_bfloat16 h = __float2bfloat16(v);
  g_xhi[i] = h;
  g_xlo[i] = __float2bfloat16(v - __bfloat162float(h));
}

// stack Wtr(64xD) and Wc(64xD) per layer into 128xD split weights
__global__ void prep_wproj(const float* __restrict__ Wtr, const float* __restrict__ Wc){
  int idx = blockIdx.x*blockDim.x + threadIdx.x;
  if (idx >= L_*128*D_) return;
  int l = idx / (128*D_);
  int rem = idx % (128*D_);
  int row = rem / D_, k = rem % D_;
  float v = (row < 64) ? Wtr[((size_t)l*64+row)*D_+k] : Wc[((size_t)l*64+row-64)*D_+k];
  __nv_bfloat16 h = __float2bfloat16(v);
  g_wphi[idx] = h;
  g_wplo[idx] = __float2bfloat16(v - __bfloat162float(h));
}

// ================= mma.sync split-bf16 GEMM, BK=64 =================
// C[m,n] = sum_k A[m,k]*B[n,k], fp32 acc, 3-term split (AhBh + AhBl + AlBh).
// BM=BN=128, BK=64, 256 threads (8 warps, 4x2), warp tile 32x64.
#define PADB 72                    // bf16 per SMEM row (64 data + 8 pad)
#define TILE_E (128*PADB)          // bf16 per tile
#define STAGE_E (4*TILE_E)         // Ahi,Alo,Bhi,Blo
#define GEMM_SMEM (2*STAGE_E*2)    // bytes (2 stages) = 147456

__device__ __forceinline__ void stage_load(
    __nv_bfloat16* s, const __nv_bfloat16* Ahi, const __nv_bfloat16* Alo,
    const __nv_bfloat16* Bhi, const __nv_bfloat16* Blo,
    int bm, int bn, int K, int k0, int tid)
{
  const __nv_bfloat16* src[4] = {Ahi, Alo, Bhi, Blo};
  #pragma unroll
  for (int t=0;t<4;t++){
    int rb = (t<2)? bm : bn;
    #pragma unroll
    for (int q=0;q<4;q++){
      int chunk = tid + q*256;          // 1024 16B-chunks per tile
      int row = chunk>>3, cc = chunk&7;
      uint32_t so = sptr(s + t*TILE_E + row*PADB + cc*8);
      cp16(so, src[t] + (size_t)(rb+row)*K + k0 + cc*8);
    }
  }
}

__global__ void __launch_bounds__(256)
gemm_mma3(const __nv_bfloat16* __restrict__ Ahi, const __nv_bfloat16* __restrict__ Alo,
          const __nv_bfloat16* __restrict__ Bhi, const __nv_bfloat16* __restrict__ Blo,
          float* __restrict__ C, int K, int Nc)
{
  extern __shared__ __nv_bfloat16 sm[];
  const int tid = threadIdx.x;
  const int wid = tid>>5, lane = tid&31;
  const int bm = blockIdx.y*128, bn = blockIdx.x*128;
  const int wm = (wid>>1)*32;
  const int wn = (wid&1)*64;
  const int KT = K>>6;

  float acc[2][8][4];
  #pragma unroll
  for (int i=0;i<2;i++)
    #pragma unroll
    for (int j=0;j<8;j++)
      #pragma unroll
      for (int q=0;q<4;q++) acc[i][j][q]=0.f;

  stage_load(sm, Ahi, Alo, Bhi, Blo, bm, bn, K, 0, tid);
  CP_COMMIT();

  const int arow = lane & 15;
  const int acol8 = (lane>>4)*8;
  const int brow = (lane&7) + ((lane>>4)<<3);
  const int bsel = ((lane>>3)&1)*8;

  for (int c=0; c<KT; c++){
    if (c+1 < KT){
      stage_load(sm + ((c+1)&1)*STAGE_E, Ahi, Alo, Bhi, Blo, bm, bn, K, (c+1)*64, tid);
      CP_COMMIT();
      CP_WAIT(1);
    } else {
      CP_WAIT(0);
    }
    __syncthreads();

    __nv_bfloat16* s = sm + (c&1)*STAGE_E;
    const uint32_t sA_hi = sptr(s);
    const uint32_t sA_lo = sA_hi + TILE_E*2;
    const uint32_t sB_hi = sA_hi + 2*TILE_E*2;
    const uint32_t sB_lo = sA_hi + 3*TILE_E*2;

    #pragma unroll
    for (int ks=0; ks<4; ks++){
      uint32_t ah[2][4], al[2][4], bh[4][4], bl[4][4];
      #pragma unroll
      for (int mi=0; mi<2; mi++){
        uint32_t off = (uint32_t)((wm + mi*16 + arow)*PADB + ks*16 + acol8)*2;
        ldsm4(ah[mi], sA_hi + off);
        ldsm4(al[mi], sA_lo + off);
      }
      #pragma unroll
      for (int p=0; p<4; p++){
        uint32_t off = (uint32_t)((wn + p*16 + brow)*PADB + ks*16 + bsel)*2;
        ldsm4(bh[p], sB_hi + off);
        ldsm4(bl[p], sB_lo + off);
      }
      #pragma unroll
      for (int mi=0; mi<2; mi++)
        #pragma unroll
        for (int p=0; p<4; p++)
          #pragma unroll
          for (int h=0; h<2; h++){
            const int ni = p*2 + h;
            mma16816(acc[mi][ni], ah[mi], &bh[p][h*2]);
            mma16816(acc[mi][ni], ah[mi], &bl[p][h*2]);
            mma16816(acc[mi][ni], al[mi], &bh[p][h*2]);
          }
    }
    __syncthreads();
  }

  #pragma unroll
  for (int mi=0; mi<2; mi++){
    const int r0 = bm + wm + mi*16 + (lane>>2);
    const int c0 = bn + wn + (lane&3)*2;
    #pragma unroll
    for (int ni=0; ni<8; ni++){
      float2 v01 = make_float2(acc[mi][ni][0], acc[mi][ni][1]);
      float2 v23 = make_float2(acc[mi][ni][2], acc[mi][ni][3]);
      *(float2*)(C + (size_t)r0*Nc + c0 + ni*8)     = v01;
      *(float2*)(C + (size_t)(r0+8)*Nc + c0 + ni*8) = v23;
    }
  }
}

// ---------------- u, v with normalization ----------------
__global__ void uv_kernel(){
  int t = blockIdx.x;
  int i = threadIdx.x;
  float uu = fabsf(g_trct[t*128 + i]);
  float vv = fabsf(g_trct[t*128 + 64 + i]);
  __shared__ float su[64], sv[64];
  su[i]=uu; sv[i]=vv; __syncthreads();
  for (int s=32; s>0; s>>=1){
    if (i<s){ su[i]+=su[i+s]; sv[i]+=sv[i+s]; }
    __syncthreads();
  }
  float scale = __fdividef(1.0f, 1e-8f + su[0]*sv[0]);
  g_u[t*TR_+i] = uu;
  g_v[t*CC_+i] = vv*scale;
}

__device__ __forceinline__ void make_decay(float ai, float bj, float& dre, float& dim){
  double rho = exp(-(double)fabsf(ai));
  double sb, cb; sincos((double)bj, &sb, &cb);
  dre = (float)(rho*cb); dim = (float)(rho*sb);
}

__global__ void scan_passA(const unsigned* __restrict__ start,
                           const float* __restrict__ a, const float* __restrict__ b,
                           int layer){
  const int i = blockIdx.y;
  const int c = blockIdx.x;
  const int j = threadIdx.x;
  const float ai = a[layer*TR_ + i];
  const float bj = b[layer*CC_ + j];
  float dre, dim;
  make_decay(ai, bj, dre, dim);
  float sre=0.f, sim=0.f;
  int reset = 0;
  const int t0 = c*CHUNK_;
  for (int t=t0; t<t0+CHUNK_; t++){
    if (start[t]){ sre=0.f; sim=0.f; reset=1; }
    float p = g_u[t*TR_+i]*g_v[t*CC_+j];
    float nre = fmaf(sre,dre, fmaf(-sim,dim,p));
    float nim = fmaf(sre,dim, sim*dre);
    sre=nre; sim=nim;
  }
  const int ch = i*CC_+j;
  g_Bend[c*NCH_+ch]=make_float2(sre,sim);
  float2 A;
  if (reset){ A=make_float2(0.f,0.f); }
  else {
    double rhoL = exp(-(double)fabsf(ai)*(double)CHUNK_);
    double sL,cL; sincos((double)bj*(double)CHUNK_, &sL,&cL);
    A = make_float2((float)(rhoL*cL), (float)(rhoL*sL));
  }
  g_Amat[c*NCH_+ch]=A;
}

__global__ void scan_passB(const float* __restrict__ state, int layer){
  int ch = blockIdx.x*blockDim.x + threadIdx.x;
  float sre = state[layer*NCH_ + ch];
  float sim = 0.f;
  #pragma unroll
  for (int c=0;c<NCHUNK_;c++){
    g_sinit[c*NCH_+ch] = make_float2(sre,sim);
    float2 A = g_Amat[c*NCH_+ch];
    float2 B = g_Bend[c*NCH_+ch];
    float nre = A.x*sre - A.y*sim + B.x;
    float nim = A.x*sim + A.y*sre + B.y;
    sre=nre; sim=nim;
  }
}

// full scan + feature emission directly in bf16 hi/lo
__global__ void scan_passC(const unsigned* __restrict__ start,
                           const float* __restrict__ a, const float* __restrict__ b,
                           int layer){
  const int i = blockIdx.y, c = blockIdx.x, j = threadIdx.x;
  float dre, dim;
  make_decay(a[layer*TR_+i], b[layer*CC_+j], dre, dim);
  const int ch = i*CC_+j;
  float2 s0 = g_sinit[c*NCH_+ch];
  float sre=s0.x, sim=s0.y;
  const int t0=c*CHUNK_;
  for (int t=t0;t<t0+CHUNK_;t++){
    if (start[t]){ sre=0.f; sim=0.f; }
    float p = g_u[t*TR_+i]*g_v[t*CC_+j];
    float nre = fmaf(sre,dre, fmaf(-sim,dim,p));
    float nim = fmaf(sre,dim, sim*dre);
    sre=nre; sim=nim;
    float r2 = fmaf(sre,sre, sim*sim);
    float f;
    if (r2 > 1e-24f){
      float rr = sqrtf(r2);
      f = __fdividef(log1pf(rr), rr);
    } else {
      f = 1.f;
    }
    float fs = f*sim, fc = f*sre;
    __nv_bfloat16 h0 = __float2bfloat16(fs);
    __nv_bfloat16 h1 = __float2bfloat16(fc);
    size_t o0 = (size_t)t*F_ + ch;
    size_t o1 = o0 + NCH_;
    g_sclhi[o0] = h0; g_scllo[o0] = __float2bfloat16(fs - __bfloat162float(h0));
    g_sclhi[o1] = h1; g_scllo[o1] = __float2bfloat16(fc - __bfloat162float(h1));
  }
}

// ================= LayerNorm + leaky ReLU =================
__device__ __forceinline__ void reduce2(float &s, float &ss){
  __shared__ float sh[8], sh2[8];
  int lane = threadIdx.x & 31, w = threadIdx.x >> 5;
  #pragma unroll
  for (int o=16;o>0;o>>=1){
    s  += __shfl_down_sync(0xffffffffu, s,  o);
    ss += __shfl_down_sync(0xffffffffu, ss, o);
  }
  if (lane==0){ sh[w]=s; sh2[w]=ss; }
  __syncthreads();
  if (w==0){
    s  = (lane<8)? sh[lane]  : 0.f;
    ss = (lane<8)? sh2[lane] : 0.f;
    #pragma unroll
    for (int o=4;o>0;o>>=1){
      s  += __shfl_down_sync(0xffffffffu, s,  o);
      ss += __shfl_down_sync(0xffffffffu, ss, o);
    }
    if (lane==0){ sh[0]=s; sh2[0]=ss; }
  }
  __syncthreads();
  s = sh[0]; ss = sh2[0];
}

__global__ void ln_leaky(const float* __restrict__ zin, const float* __restrict__ bias,
                         const float* __restrict__ gamma, const float* __restrict__ beta,
                         float* __restrict__ zout, float* __restrict__ xacc,
                         __nv_bfloat16* __restrict__ zhi, __nv_bfloat16* __restrict__ zlo,
                         __nv_bfloat16* __restrict__ xhi, __nv_bfloat16* __restrict__ xlo){
  const int t = blockIdx.x;
  const int tid = threadIdx.x;
  float v0 = zin[t*D_ + tid]       + bias[tid];
  float v1 = zin[t*D_ + 256 + tid] + bias[256+tid];
  float s = v0+v1;
  float ss = v0*v0 + v1*v1;
  reduce2(s, ss);
  float m = s * (1.f/512.f);
  float var = ss * (1.f/512.f) - m*m;
  float rinv = rsqrtf(var + 1e-5f);
  float y0 = (v0 - m)*rinv*gamma[tid]     + beta[tid];
  float y1 = (v1 - m)*rinv*gamma[256+tid] + beta[256+tid];
  y0 = (y0 > 0.f) ? y0 : 0.01f*y0;
  y1 = (y1 > 0.f) ? y1 : 0.01f*y1;
  if (zout){
    zout[t*D_ + tid]       = y0;
    zout[t*D_ + 256 + tid] = y1;
  }
  if (xacc){
    float x0 = xacc[t*D_ + tid]       + y0;
    float x1 = xacc[t*D_ + 256 + tid] + y1;
    xacc[t*D_ + tid]       = x0;
    xacc[t*D_ + 256 + tid] = x1;
    if (xhi){
      __nv_bfloat16 h0 = __float2bfloat16(x0);
      __nv_bfloat16 h1 = __float2bfloat16(x1);
      xhi[t*D_ + tid]       = h0;
      xhi[t*D_ + 256 + tid] = h1;
      xlo[t*D_ + tid]       = __float2bfloat16(x0 - __bfloat162float(h0));
      xlo[t*D_ + 256 + tid] = __float2bfloat16(x1 - __bfloat162float(h1));
    }
  }
  if (zhi){
    __nv_bfloat16 h0 = __float2bfloat16(y0);
    __nv_bfloat16 h1 = __float2bfloat16(y1);
    zhi[t*D_ + tid]       = h0;
    zhi[t*D_ + 256 + tid] = h1;
    zlo[t*D_ + tid]       = __float2bfloat16(y0 - __bfloat162float(h0));
    zlo[t*D_ + 256 + tid] = __float2bfloat16(y1 - __bfloat162float(h1));
  }
}

// ================= launcher =================
extern "C" void kernel_launch(void* const* d_in, const int* in_sizes, int n_in,
                              void* d_out, int out_size) {
  const float*    x     = (const float*)d_in[0];
  const float*    state = (const float*)d_in[1];
  const unsigned* start = (const unsigned*)d_in[2];
  const float*    Wtr   = (const float*)d_in[3];
  const float*    Wc    = (const float*)d_in[4];
  const float*    a     = (const float*)d_in[5];
  const float*    b     = (const float*)d_in[6];
  const float*    W0    = (const float*)d_in[7];
  const float*    b0    = (const float*)d_in[8];
  const float*    g0    = (const float*)d_in[9];
  const float*    beta0 = (const float*)d_in[10];
  const float*    W1    = (const float*)d_in[11];
  const float*    b1    = (const float*)d_in[12];
  const float*    g1    = (const float*)d_in[13];
  const float*    beta1 = (const float*)d_in[14];
  float* out = (float*)d_out;

  float *px, *ptrct, *ph, *pzt;
  __nv_bfloat16 *pshi, *pslo, *pw0h, *pw0l, *pw1h, *pw1l, *pwph, *pwpl;
  __nv_bfloat16 *pz0h, *pz0l, *pxh, *pxl;
  cudaGetSymbolAddress((void**)&px,    g_x);
  cudaGetSymbolAddress((void**)&ptrct, g_trct);
  cudaGetSymbolAddress((void**)&ph,    g_h);
  cudaGetSymbolAddress((void**)&pzt,   g_ztmp);
  cudaGetSymbolAddress((void**)&pshi,  g_sclhi);
  cudaGetSymbolAddress((void**)&pslo,  g_scllo);
  cudaGetSymbolAddress((void**)&pw0h,  g_w0hi);
  cudaGetSymbolAddress((void**)&pw0l,  g_w0lo);
  cudaGetSymbolAddress((void**)&pw1h,  g_w1hi);
  cudaGetSymbolAddress((void**)&pw1l,  g_w1lo);
  cudaGetSymbolAddress((void**)&pwph,  g_wphi);
  cudaGetSymbolAddress((void**)&pwpl,  g_wplo);
  cudaGetSymbolAddress((void**)&pz0h,  g_z0hi);
  cudaGetSymbolAddress((void**)&pz0l,  g_z0lo);
  cudaGetSymbolAddress((void**)&pxh,   g_xhi);
  cudaGetSymbolAddress((void**)&pxl,   g_xlo);

  cudaFuncSetAttribute(gemm_mma3, cudaFuncAttributeMaxDynamicSharedMemorySize, GEMM_SMEM);

  copy_split_x<<<(T_*D_)/256, 256>>>(x);
  split_f32<<<(L_*D_*F_ + 255)/256, 256>>>(W0, pw0h, pw0l, L_*D_*F_);
  split_f32<<<(L_*D_*D_ + 255)/256, 256>>>(W1, pw1h, pw1l, L_*D_*D_);
  prep_wproj<<<(L_*128*D_ + 255)/256, 256>>>(Wtr, Wc);

  for (int l=0; l<L_; l++){
    // [tr|ct] = x @ [Wtr;Wc]^T  (M=4096, N=128, K=512) on tensor path
    gemm_mma3<<<dim3(1, T_/128), 256, GEMM_SMEM>>>(
        pxh, pxl, pwph + (size_t)l*128*D_, pwpl + (size_t)l*128*D_, ptrct, D_, 128);
    uv_kernel<<<T_, 64>>>();

    scan_passA<<<dim3(NCHUNK_, TR_), CC_>>>(start, a, b, l);
    scan_passB<<<NCH_/256, 256>>>(state, l);
    scan_passC<<<dim3(NCHUNK_, TR_), CC_>>>(start, a, b, l);

    // h = scaled @ W0^T   (M=4096, N=512, K=8192)
    gemm_mma3<<<dim3(D_/128, T_/128), 256, GEMM_SMEM>>>(
        pshi, pslo, pw0h + (size_t)l*D_*F_, pw0l + (size_t)l*D_*F_, ph, F_, D_);
    ln_leaky<<<T_, 256>>>(ph, b0 + l*D_, g0 + l*D_, beta0 + l*D_,
                          nullptr, nullptr, pz0h, pz0l, nullptr, nullptr);

    // h = z0 @ W1^T   (M=4096, N=512, K=512)
    gemm_mma3<<<dim3(D_/128, T_/128), 256, GEMM_SMEM>>>(
        pz0h, pz0l, pw1h + (size_t)l*D_*D_, pw1l + (size_t)l*D_*D_, ph, D_, D_);
    float* zo = (l == L_-1) ? out : pzt;
    bool last = (l == L_-1);
    ln_leaky<<<T_, 256>>>(ph, b1 + l*D_, g1 + l*D_, beta1 + l*D_,
                          zo, px, nullptr, nullptr,
                          last ? nullptr : pxh, last ? nullptr : pxl);
  }
}